// round 4
// baseline (speedup 1.0000x reference)
#include <cuda_runtime.h>
#include <math.h>

// Problem constants
#define T_TOK 8192
#define DDIM  4096
#define NEXP  64
#define TOPK  8

// Tiling
#define BM    64
#define BK    16
#define NTH   256
#define NITER (DDIM / BK)     // 256
#define HITER (NITER / 2)     // 128  (split-K = 2, contiguous halves)

// ----------------------------------------------------------------------------
// Fused router: fp32 GEMM computed as TWO serial fmaf chains over contiguous
// K halves (k<2048 and k>=2048), combined lo+hi — replicating a split-K=2
// fp32 GEMM's rounding. Then per-token top-8 (tie: lowest index, matching
// jax.lax.top_k) + softmax. Block: 64 tokens x 64 experts, 256 thr, 4x4 tile.
// ----------------------------------------------------------------------------
__global__ __launch_bounds__(NTH)
void router_fused(const float* __restrict__ x, const float* __restrict__ w,
                  float* __restrict__ out, int half)
{
    __shared__ float Xs[BK][BM];     // [k][token]
    __shared__ float Ws[BK][NEXP];   // [k][expert]
    __shared__ float Ls[BM][NEXP];   // logits

    const int tid = threadIdx.x;
    const int t0  = blockIdx.x * BM;

    const int tt = tid & 15;         // token group  -> 4 tokens
    const int et = tid >> 4;         // expert group -> 4 experts

    float accA[4][4], accB[4][4];
#pragma unroll
    for (int i = 0; i < 4; i++)
#pragma unroll
        for (int j = 0; j < 4; j++) { accA[i][j] = 0.0f; accB[i][j] = 0.0f; }

    // staging assignments
    const int xt = tid >> 2;          // 0..63  token row
    const int xk = (tid & 3) * 4;     // 0,4,8,12 within BK
    const int wk = tid >> 4;          // 0..15  k row
    const int we = (tid & 15) * 4;    // expert col

    const float* xptr = x + (size_t)(t0 + xt) * DDIM + xk;
    const float* wptr = w + (size_t)wk * NEXP + we;

    // software pipeline: prime
    float4 xr = *(const float4*)xptr;
    float4 wr = *(const float4*)wptr;

    for (int it = 0; it < NITER; ++it) {
        __syncthreads();   // previous tile consumed
        Xs[xk + 0][xt] = xr.x;
        Xs[xk + 1][xt] = xr.y;
        Xs[xk + 2][xt] = xr.z;
        Xs[xk + 3][xt] = xr.w;
        *(float4*)&Ws[wk][we] = wr;
        __syncthreads();

        if (it + 1 < NITER) {
            xr = *(const float4*)(xptr + (it + 1) * BK);
            wr = *(const float4*)(wptr + (size_t)(it + 1) * BK * NEXP);
        }

        if (it < HITER) {
#pragma unroll
            for (int kk = 0; kk < BK; ++kk) {
                float4 a = *(const float4*)&Xs[kk][tt * 4];
                float4 b = *(const float4*)&Ws[kk][et * 4];
                float av[4] = {a.x, a.y, a.z, a.w};
                float bv[4] = {b.x, b.y, b.z, b.w};
#pragma unroll
                for (int i = 0; i < 4; i++)
#pragma unroll
                    for (int j = 0; j < 4; j++)
                        accA[i][j] = fmaf(av[i], bv[j], accA[i][j]);
            }
        } else {
#pragma unroll
            for (int kk = 0; kk < BK; ++kk) {
                float4 a = *(const float4*)&Xs[kk][tt * 4];
                float4 b = *(const float4*)&Ws[kk][et * 4];
                float av[4] = {a.x, a.y, a.z, a.w};
                float bv[4] = {b.x, b.y, b.z, b.w};
#pragma unroll
                for (int i = 0; i < 4; i++)
#pragma unroll
                    for (int j = 0; j < 4; j++)
                        accB[i][j] = fmaf(av[i], bv[j], accB[i][j]);
            }
        }
    }

    // combine split-K halves in ascending slice order, stage logits to smem
    __syncthreads();
#pragma unroll
    for (int i = 0; i < 4; i++)
#pragma unroll
        for (int j = 0; j < 4; j++)
            Ls[tt * 4 + i][et * 4 + j] = accA[i][j] + accB[i][j];
    __syncthreads();

    // ---- top-8 + softmax: one warp handles 8 tokens ----
    const int warp = tid >> 5;
    const int lane = tid & 31;

    for (int tk = 0; tk < 8; ++tk) {
        const int tok = warp * 8 + tk;
        float v0 = Ls[tok][lane];
        float v1 = Ls[tok][lane + 32];

        float topv[TOPK];
        int   topi[TOPK];
#pragma unroll
        for (int j = 0; j < TOPK; j++) {
            float bv; int bi;
            if (v0 >= v1) { bv = v0; bi = lane; }
            else          { bv = v1; bi = lane + 32; }
#pragma unroll
            for (int off = 16; off; off >>= 1) {
                float ov = __shfl_xor_sync(0xffffffffu, bv, off);
                int   oi = __shfl_xor_sync(0xffffffffu, bi, off);
                if (ov > bv || (ov == bv && oi < bi)) { bv = ov; bi = oi; }
            }
            topv[j] = bv;
            topi[j] = bi;
            if (bi == lane)           v0 = -INFINITY;
            else if (bi == lane + 32) v1 = -INFINITY;
        }

        const float mx = topv[0];
        float e[TOPK];
        float sum = 0.0f;
#pragma unroll
        for (int j = 0; j < TOPK; j++) { e[j] = expf(topv[j] - mx); sum += e[j]; }
        const float inv = 1.0f / sum;

        if (lane < TOPK) {
            const size_t g = (size_t)(t0 + tok) * TOPK + lane;
            out[g]        = e[lane] * inv;
            out[half + g] = (float)topi[lane];
        }
    }
}

// ----------------------------------------------------------------------------
extern "C" void kernel_launch(void* const* d_in, const int* in_sizes, int n_in,
                              void* d_out, int out_size)
{
    const float* x = (const float*)d_in[0];
    const float* w = (const float*)d_in[1];
    float* out = (float*)d_out;
    const int half = out_size >> 1;

    router_fused<<<T_TOK / BM, NTH>>>(x, w, out, half);
}